// round 9
// baseline (speedup 1.0000x reference)
#include <cuda_runtime.h>
#include <cuda_fp16.h>

#define NN 100000
#define NE 1600000
#define DD 128
#define LN_EPS 1e-5f
#define CAP 64    // max degree capacity (Poisson(16): P(deg>=64) ~ 1e-18)
#define MB 128    // nodes per gemm block
#define LDA 136   // smem row stride in halves (128 + 8 pad -> conflict-free LDSM)

// ---------------- scratch ----------------------------------------------------
__device__ int   g_cnt[NN];
__device__ int   g_slot[NN * CAP];    // per-node dst buckets (25.6MB, L2-resident)
__device__ uint4 g_xs4[NN * 16];      // fp16 x*invdeg, [node][128] 8 halves/uint4
__device__ uint4 g_nh4[NN * 16];      // fp16 neigh,     same layout
__device__ uint4 g_Wh4[DD * DD / 8];  // fp16 W, row-major [j][k] (== B col-major)

// ---------------- bucket build -----------------------------------------------
__global__ void k_zero() {
    int i = blockIdx.x * blockDim.x + threadIdx.x;
    if (i < NN) g_cnt[i] = 0;
}

__global__ void k_scat(const int4* __restrict__ src4,
                       const int4* __restrict__ dst4) {
    int i = blockIdx.x * blockDim.x + threadIdx.x;
    if (i < NE / 8) {
        int4 sa = src4[2 * i], sb = src4[2 * i + 1];
        int4 da = dst4[2 * i], db = dst4[2 * i + 1];
        int p0 = atomicAdd(&g_cnt[sa.x], 1);
        int p1 = atomicAdd(&g_cnt[sa.y], 1);
        int p2 = atomicAdd(&g_cnt[sa.z], 1);
        int p3 = atomicAdd(&g_cnt[sa.w], 1);
        int p4 = atomicAdd(&g_cnt[sb.x], 1);
        int p5 = atomicAdd(&g_cnt[sb.y], 1);
        int p6 = atomicAdd(&g_cnt[sb.z], 1);
        int p7 = atomicAdd(&g_cnt[sb.w], 1);
        g_slot[sa.x * CAP + p0] = da.x;
        g_slot[sa.y * CAP + p1] = da.y;
        g_slot[sa.z * CAP + p2] = da.z;
        g_slot[sa.w * CAP + p3] = da.w;
        g_slot[sb.x * CAP + p4] = db.x;
        g_slot[sb.y * CAP + p5] = db.y;
        g_slot[sb.z * CAP + p6] = db.z;
        g_slot[sb.w * CAP + p7] = db.w;
    }
}

// ---------------- conv: xs = fp16(x*invdeg); Wh = fp16(W) --------------------
__global__ void k_conv(const float4* __restrict__ x4,
                       const float4* __restrict__ W4) {
    int i = blockIdx.x * blockDim.x + threadIdx.x;
    if (i < NN * 16) {
        int node = i >> 4, c = i & 15;
        int d = g_cnt[node];
        float s = 1.0f / (float)(d > 1 ? d : 1);
        float4 v0 = x4[node * 32 + c * 2];
        float4 v1 = x4[node * 32 + c * 2 + 1];
        __half2 h0 = __floats2half2_rn(v0.x * s, v0.y * s);
        __half2 h1 = __floats2half2_rn(v0.z * s, v0.w * s);
        __half2 h2 = __floats2half2_rn(v1.x * s, v1.y * s);
        __half2 h3 = __floats2half2_rn(v1.z * s, v1.w * s);
        uint4 u;
        u.x = *(unsigned*)&h0; u.y = *(unsigned*)&h1;
        u.z = *(unsigned*)&h2; u.w = *(unsigned*)&h3;
        g_xs4[i] = u;
    } else if (i < NN * 16 + DD * DD / 8) {
        int j = i - NN * 16;
        float4 v0 = W4[j * 2];
        float4 v1 = W4[j * 2 + 1];
        __half2 h0 = __floats2half2_rn(v0.x, v0.y);
        __half2 h1 = __floats2half2_rn(v0.z, v0.w);
        __half2 h2 = __floats2half2_rn(v1.x, v1.y);
        __half2 h3 = __floats2half2_rn(v1.z, v1.w);
        uint4 u;
        u.x = *(unsigned*)&h0; u.y = *(unsigned*)&h1;
        u.z = *(unsigned*)&h2; u.w = *(unsigned*)&h3;
        g_Wh4[j] = u;
    }
}

// ---------------- gather: warp/node, fp16 HADD2 banks, no F2F in loop --------
__device__ __forceinline__ void hacc(__half2* b, uint4 p) {
    __half2* q = (__half2*)&p;
    b[0] = __hadd2(b[0], q[0]);
    b[1] = __hadd2(b[1], q[1]);
    b[2] = __hadd2(b[2], q[2]);
    b[3] = __hadd2(b[3], q[3]);
}

__global__ void k_gather() {
    int gw = (blockIdx.x * blockDim.x + threadIdx.x) >> 5;
    int lane = threadIdx.x & 31;
    if (gw >= NN) return;
    int n = g_cnt[gw];
    const int* slots = &g_slot[gw * CAP];
    int hw = lane >> 4, l16 = lane & 15;

    const uint4 z4 = make_uint4(0u, 0u, 0u, 0u);
    __half2 zero = __float2half2_rn(0.f);
    __half2 b0[4] = {zero, zero, zero, zero};
    __half2 b1[4] = {zero, zero, zero, zero};
    __half2 b2[4] = {zero, zero, zero, zero};
    __half2 b3[4] = {zero, zero, zero, zero};

    int e = 0;
    for (; e + 8 <= n; e += 8) {   // 8 edges: 4 independent uint4 loads + banks
        int d0 = slots[e + hw];
        int d1 = slots[e + 2 + hw];
        int d2 = slots[e + 4 + hw];
        int d3 = slots[e + 6 + hw];
        uint4 p0 = g_xs4[d0 * 16 + l16];
        uint4 p1 = g_xs4[d1 * 16 + l16];
        uint4 p2 = g_xs4[d2 * 16 + l16];
        uint4 p3 = g_xs4[d3 * 16 + l16];
        hacc(b0, p0); hacc(b1, p1); hacc(b2, p2); hacc(b3, p3);
    }
    if (e + 4 <= n) {              // 4-edge tail (uniform, no divergence)
        int d0 = slots[e + hw];
        int d1 = slots[e + 2 + hw];
        uint4 p0 = g_xs4[d0 * 16 + l16];
        uint4 p1 = g_xs4[d1 * 16 + l16];
        hacc(b0, p0); hacc(b1, p1);
        e += 4;
    }
    {                              // predicated pair tails, all lanes uniform
        int i0 = e + hw;
        bool m = i0 < n;
        int dc = m ? slots[i0] : 0;
        uint4 p = g_xs4[dc * 16 + l16];
        if (!m) p = z4;
        hacc(b2, p);
        int i1 = e + 2 + hw;
        bool m1 = i1 < n;
        int dc1 = m1 ? slots[i1] : 0;
        uint4 p1 = g_xs4[dc1 * 16 + l16];
        if (!m1) p1 = z4;
        hacc(b3, p1);
    }

    // combine banks in fp16, convert once, reduce across half-warps in fp32
    #pragma unroll
    for (int i = 0; i < 4; i++) {
        b0[i] = __hadd2(__hadd2(b0[i], b1[i]), __hadd2(b2[i], b3[i]));
    }
    float a[8];
    #pragma unroll
    for (int i = 0; i < 4; i++) {
        float2 f = __half22float2(b0[i]);
        a[2 * i] = f.x; a[2 * i + 1] = f.y;
    }
    #pragma unroll
    for (int i = 0; i < 8; i++)
        a[i] += __shfl_xor_sync(0xffffffffu, a[i], 16);
    if (hw == 0) {
        __half2 h0 = __floats2half2_rn(a[0], a[1]);
        __half2 h1 = __floats2half2_rn(a[2], a[3]);
        __half2 h2 = __floats2half2_rn(a[4], a[5]);
        __half2 h3 = __floats2half2_rn(a[6], a[7]);
        uint4 u;
        u.x = *(unsigned*)&h0; u.y = *(unsigned*)&h1;
        u.z = *(unsigned*)&h2; u.w = *(unsigned*)&h3;
        g_nh4[gw * 16 + l16] = u;
    }
}

// ---------------- mma helpers ------------------------------------------------
__device__ __forceinline__ void ldsm_x4(unsigned* r, const __half* p) {
    unsigned addr = (unsigned)__cvta_generic_to_shared(p);
    asm volatile("ldmatrix.sync.aligned.m8n8.x4.shared.b16 {%0,%1,%2,%3}, [%4];"
                 : "=r"(r[0]), "=r"(r[1]), "=r"(r[2]), "=r"(r[3]) : "r"(addr));
}
__device__ __forceinline__ void mma16816(float* c, const unsigned* a,
                                         unsigned b0, unsigned b1) {
    asm volatile(
        "mma.sync.aligned.m16n8k16.row.col.f32.f16.f16.f32 "
        "{%0,%1,%2,%3}, {%4,%5,%6,%7}, {%8,%9}, {%0,%1,%2,%3};"
        : "+f"(c[0]), "+f"(c[1]), "+f"(c[2]), "+f"(c[3])
        : "r"(a[0]), "r"(a[1]), "r"(a[2]), "r"(a[3]), "r"(b0), "r"(b1));
}

// ---------------- HMMA GEMM + bias + residual + LayerNorm --------------------
__global__ void __launch_bounds__(256, 2)
k_gemmln(const float2* __restrict__ x2,
         const float2* __restrict__ bias2,
         const float2* __restrict__ gamma2,
         const float2* __restrict__ beta2,
         float2* __restrict__ out2) {
    extern __shared__ __half sh[];
    __half* sA = sh;              // [128][LDA]
    __half* sB = sh + MB * LDA;   // [128][LDA]
    int t = threadIdx.x, lane = t & 31, warp = t >> 5;
    int n0 = blockIdx.x * MB;

    for (int i = t; i < MB * 16; i += 256) {
        int r = i >> 4, c = i & 15;
        uint4 v = (n0 + r < NN) ? g_nh4[(n0 + r) * 16 + c]
                                : make_uint4(0u, 0u, 0u, 0u);
        *(uint4*)&sA[r * LDA + c * 8] = v;
    }
    for (int i = t; i < DD * 16; i += 256) {
        int r = i >> 4, c = i & 15;
        *(uint4*)&sB[r * LDA + c * 8] = g_Wh4[r * 16 + c];
    }
    __syncthreads();

    int mr = warp * 16;
    int arow = mr + (lane & 15);
    int acol = (lane >> 4) * 8;
    unsigned af[8][4];
    #pragma unroll
    for (int kc = 0; kc < 8; kc++)
        ldsm_x4(af[kc], &sA[arow * LDA + kc * 16 + acol]);

    float acc[16][4];
    #pragma unroll
    for (int i = 0; i < 16; i++)
        #pragma unroll
        for (int j = 0; j < 4; j++) acc[i][j] = 0.f;

    int brow_off = (lane & 7) + ((lane >> 4) << 3);
    int bcol = lane & 8;
    #pragma unroll
    for (int p = 0; p < 8; p++) {
        int j0 = p * 16;
        #pragma unroll
        for (int kc = 0; kc < 8; kc++) {
            unsigned bf[4];
            ldsm_x4(bf, &sB[(j0 + brow_off) * LDA + kc * 16 + bcol]);
            mma16816(acc[2 * p],     af[kc], bf[0], bf[1]);
            mma16816(acc[2 * p + 1], af[kc], bf[2], bf[3]);
        }
    }

    int qrow = lane >> 2;
    int qcol = (lane & 3) * 2;
    int row_lo = n0 + mr + qrow;
    int row_hi = row_lo + 8;
    bool ok_lo = row_lo < NN, ok_hi = row_hi < NN;
    float s_lo = 0.f, ss_lo = 0.f, s_hi = 0.f, ss_hi = 0.f;
    #pragma unroll
    for (int t16 = 0; t16 < 16; t16++) {
        int n = (t16 >> 1) * 16 + (t16 & 1) * 8 + qcol;
        float2 bb = bias2[n >> 1];
        float2 xl = ok_lo ? x2[row_lo * 64 + (n >> 1)] : make_float2(0.f, 0.f);
        float2 xh = ok_hi ? x2[row_hi * 64 + (n >> 1)] : make_float2(0.f, 0.f);
        float h0 = acc[t16][0] + xl.x + bb.x;
        float h1 = acc[t16][1] + xl.y + bb.y;
        float h2 = acc[t16][2] + xh.x + bb.x;
        float h3 = acc[t16][3] + xh.y + bb.y;
        acc[t16][0] = h0; acc[t16][1] = h1; acc[t16][2] = h2; acc[t16][3] = h3;
        s_lo += h0 + h1; ss_lo += h0 * h0 + h1 * h1;
        s_hi += h2 + h3; ss_hi += h2 * h2 + h3 * h3;
    }
    #pragma unroll
    for (int o = 1; o <= 2; o <<= 1) {
        s_lo  += __shfl_xor_sync(0xffffffffu, s_lo,  o);
        ss_lo += __shfl_xor_sync(0xffffffffu, ss_lo, o);
        s_hi  += __shfl_xor_sync(0xffffffffu, s_hi,  o);
        ss_hi += __shfl_xor_sync(0xffffffffu, ss_hi, o);
    }
    float m_lo = s_lo * (1.0f / 128.0f);
    float v_lo = ss_lo * (1.0f / 128.0f) - m_lo * m_lo;
    float r_lo = rsqrtf(v_lo + LN_EPS);
    float m_hi = s_hi * (1.0f / 128.0f);
    float v_hi = ss_hi * (1.0f / 128.0f) - m_hi * m_hi;
    float r_hi = rsqrtf(v_hi + LN_EPS);

    #pragma unroll
    for (int t16 = 0; t16 < 16; t16++) {
        int n = (t16 >> 1) * 16 + (t16 & 1) * 8 + qcol;
        float2 gg = gamma2[n >> 1];
        float2 tt = beta2[n >> 1];
        if (ok_lo) {
            float2 o;
            o.x = (acc[t16][0] - m_lo) * r_lo * gg.x + tt.x;
            o.y = (acc[t16][1] - m_lo) * r_lo * gg.y + tt.y;
            out2[row_lo * 64 + (n >> 1)] = o;
        }
        if (ok_hi) {
            float2 o;
            o.x = (acc[t16][2] - m_hi) * r_hi * gg.x + tt.x;
            o.y = (acc[t16][3] - m_hi) * r_hi * gg.y + tt.y;
            out2[row_hi * 64 + (n >> 1)] = o;
        }
    }
}

// ---------------- launch -----------------------------------------------------
extern "C" void kernel_launch(void* const* d_in, const int* in_sizes, int n_in,
                              void* d_out, int out_size) {
    const float* x     = (const float*)d_in[0];
    const float* W     = (const float*)d_in[1];
    const float* bias  = (const float*)d_in[2];
    const float* gamma = (const float*)d_in[3];
    const float* beta  = (const float*)d_in[4];
    const int*   ei    = (const int*)d_in[5];
    const int4*  src4  = (const int4*)ei;
    const int4*  dst4  = (const int4*)(ei + NE);

    const int smem = (MB + DD) * LDA * (int)sizeof(__half);  // 69632B
    cudaFuncSetAttribute(k_gemmln, cudaFuncAttributeMaxDynamicSharedMemorySize, smem);

    k_zero<<<(NN + 255) / 256, 256>>>();
    k_scat<<<(NE / 8 + 255) / 256, 256>>>(src4, dst4);
    k_conv<<<(NN * 16 + DD * DD / 8 + 255) / 256, 256>>>(
        (const float4*)x, (const float4*)W);
    k_gather<<<(NN * 32 + 255) / 256, 256>>>();
    k_gemmln<<<(NN + MB - 1) / MB, 256, smem>>>(
        (const float2*)x, (const float2*)bias, (const float2*)gamma,
        (const float2*)beta, (float2*)d_out);
}

// round 11
// speedup vs baseline: 1.0614x; 1.0614x over previous
#include <cuda_runtime.h>
#include <cuda_fp16.h>

#define NN 100000
#define NE 1600000
#define DD 128
#define LN_EPS 1e-5f
#define CAP 64    // max degree capacity (Poisson(16): P(deg>=64) ~ 1e-18)
#define MB 128    // nodes per gemm block
#define LDA 136   // smem row stride in halves (128 + 8 pad -> conflict-free LDSM)

// ---------------- scratch ----------------------------------------------------
__device__ int   g_cnt[NN];
__device__ float g_ideg[NN];
__device__ int   g_slot[NN * CAP];    // per-node dst buckets (25.6MB, L2-resident)
__device__ uint4 g_xs4[NN * 16];      // fp16 x (UNSCALED), [node][128] 8 halves/uint4
__device__ uint4 g_nh4[NN * 16];      // fp16 neigh, same layout
__device__ uint4 g_Wh4[DD * DD / 8];  // fp16 W, row-major [j][k] (== B col-major)

// ---------------- zero -------------------------------------------------------
__global__ void k_zero() {
    int i = blockIdx.x * blockDim.x + threadIdx.x;
    if (i < NN) g_cnt[i] = 0;
}

// ---------------- scat + conv fused (grid-split; conv independent of scat) ---
#define SCAT_BLKS ((NE / 8 + 255) / 256)
__global__ void k_scatconv(const int4* __restrict__ src4,
                           const int4* __restrict__ dst4,
                           const float4* __restrict__ x4,
                           const float4* __restrict__ W4) {
    if (blockIdx.x < SCAT_BLKS) {
        int i = blockIdx.x * blockDim.x + threadIdx.x;
        if (i < NE / 8) {
            int4 sa = src4[2 * i], sb = src4[2 * i + 1];
            int4 da = dst4[2 * i], db = dst4[2 * i + 1];
            int p0 = atomicAdd(&g_cnt[sa.x], 1);
            int p1 = atomicAdd(&g_cnt[sa.y], 1);
            int p2 = atomicAdd(&g_cnt[sa.z], 1);
            int p3 = atomicAdd(&g_cnt[sa.w], 1);
            int p4 = atomicAdd(&g_cnt[sb.x], 1);
            int p5 = atomicAdd(&g_cnt[sb.y], 1);
            int p6 = atomicAdd(&g_cnt[sb.z], 1);
            int p7 = atomicAdd(&g_cnt[sb.w], 1);
            g_slot[sa.x * CAP + p0] = da.x;
            g_slot[sa.y * CAP + p1] = da.y;
            g_slot[sa.z * CAP + p2] = da.z;
            g_slot[sa.w * CAP + p3] = da.w;
            g_slot[sb.x * CAP + p4] = db.x;
            g_slot[sb.y * CAP + p5] = db.y;
            g_slot[sb.z * CAP + p6] = db.z;
            g_slot[sb.w * CAP + p7] = db.w;
        }
    } else {
        int i = (blockIdx.x - SCAT_BLKS) * blockDim.x + threadIdx.x;
        if (i < NN * 16) {
            float4 v0 = x4[i * 2];
            float4 v1 = x4[i * 2 + 1];
            __half2 h0 = __floats2half2_rn(v0.x, v0.y);
            __half2 h1 = __floats2half2_rn(v0.z, v0.w);
            __half2 h2 = __floats2half2_rn(v1.x, v1.y);
            __half2 h3 = __floats2half2_rn(v1.z, v1.w);
            uint4 u;
            u.x = *(unsigned*)&h0; u.y = *(unsigned*)&h1;
            u.z = *(unsigned*)&h2; u.w = *(unsigned*)&h3;
            g_xs4[i] = u;
        } else if (i < NN * 16 + DD * DD / 8) {
            int j = i - NN * 16;
            float4 v0 = W4[j * 2];
            float4 v1 = W4[j * 2 + 1];
            __half2 h0 = __floats2half2_rn(v0.x, v0.y);
            __half2 h1 = __floats2half2_rn(v0.z, v0.w);
            __half2 h2 = __floats2half2_rn(v1.x, v1.y);
            __half2 h3 = __floats2half2_rn(v1.z, v1.w);
            uint4 u;
            u.x = *(unsigned*)&h0; u.y = *(unsigned*)&h1;
            u.z = *(unsigned*)&h2; u.w = *(unsigned*)&h3;
            g_Wh4[j] = u;
        }
    }
}

// ---------------- prep: invdeg (after scat) ----------------------------------
__global__ void k_prep() {
    int i = blockIdx.x * blockDim.x + threadIdx.x;
    if (i < NN) {
        int d = g_cnt[i];
        g_ideg[i] = 1.0f / (float)(d > 1 ? d : 1);
    }
}

// ---------------- gather: warp/node, fp32 FFMA accumulation, 8-edge unroll ---
__device__ __forceinline__ void facc(float* a, uint4 p, float w) {
    __half2* hp = (__half2*)&p;
    #pragma unroll
    for (int i = 0; i < 4; i++) {
        float2 f = __half22float2(hp[i]);
        a[2 * i]     = fmaf(f.x, w, a[2 * i]);
        a[2 * i + 1] = fmaf(f.y, w, a[2 * i + 1]);
    }
}

__global__ void k_gather() {
    int gw = (blockIdx.x * blockDim.x + threadIdx.x) >> 5;
    int lane = threadIdx.x & 31;
    if (gw >= NN) return;
    int n = g_cnt[gw];
    const int* slots = &g_slot[gw * CAP];
    int hw = lane >> 4, l16 = lane & 15;
    float a[8] = {0.f, 0.f, 0.f, 0.f, 0.f, 0.f, 0.f, 0.f};
    int e = 0;
    for (; e + 8 <= n; e += 8) {   // 8 edges: 4 uint4 in flight per lane
        int d0 = slots[e + hw];
        int d1 = slots[e + 2 + hw];
        int d2 = slots[e + 4 + hw];
        int d3 = slots[e + 6 + hw];
        float w0 = g_ideg[d0], w1 = g_ideg[d1];
        float w2 = g_ideg[d2], w3 = g_ideg[d3];
        uint4 p0 = g_xs4[d0 * 16 + l16];
        uint4 p1 = g_xs4[d1 * 16 + l16];
        uint4 p2 = g_xs4[d2 * 16 + l16];
        uint4 p3 = g_xs4[d3 * 16 + l16];
        facc(a, p0, w0); facc(a, p1, w1); facc(a, p2, w2); facc(a, p3, w3);
    }
    if (e + 4 <= n) {
        int d0 = slots[e + hw];
        int d1 = slots[e + 2 + hw];
        float w0 = g_ideg[d0], w1 = g_ideg[d1];
        uint4 p0 = g_xs4[d0 * 16 + l16];
        uint4 p1 = g_xs4[d1 * 16 + l16];
        facc(a, p0, w0); facc(a, p1, w1);
        e += 4;
    }
    for (; e < n; e += 2) {
        if (e + hw < n) {
            int d0 = slots[e + hw];
            facc(a, g_xs4[d0 * 16 + l16], g_ideg[d0]);
        }
    }
    #pragma unroll
    for (int i = 0; i < 8; i++)
        a[i] += __shfl_xor_sync(0xffffffffu, a[i], 16);
    if (hw == 0) {
        __half2 h0 = __floats2half2_rn(a[0], a[1]);
        __half2 h1 = __floats2half2_rn(a[2], a[3]);
        __half2 h2 = __floats2half2_rn(a[4], a[5]);
        __half2 h3 = __floats2half2_rn(a[6], a[7]);
        uint4 u;
        u.x = *(unsigned*)&h0; u.y = *(unsigned*)&h1;
        u.z = *(unsigned*)&h2; u.w = *(unsigned*)&h3;
        g_nh4[gw * 16 + l16] = u;
    }
}

// ---------------- mma helpers ------------------------------------------------
__device__ __forceinline__ void ldsm_x4(unsigned* r, const __half* p) {
    unsigned addr = (unsigned)__cvta_generic_to_shared(p);
    asm volatile("ldmatrix.sync.aligned.m8n8.x4.shared.b16 {%0,%1,%2,%3}, [%4];"
                 : "=r"(r[0]), "=r"(r[1]), "=r"(r[2]), "=r"(r[3]) : "r"(addr));
}
__device__ __forceinline__ void mma16816(float* c, const unsigned* a,
                                         unsigned b0, unsigned b1) {
    asm volatile(
        "mma.sync.aligned.m16n8k16.row.col.f32.f16.f16.f32 "
        "{%0,%1,%2,%3}, {%4,%5,%6,%7}, {%8,%9}, {%0,%1,%2,%3};"
        : "+f"(c[0]), "+f"(c[1]), "+f"(c[2]), "+f"(c[3])
        : "r"(a[0]), "r"(a[1]), "r"(a[2]), "r"(a[3]), "r"(b0), "r"(b1));
}

// ---------------- HMMA GEMM + bias + residual + LayerNorm --------------------
__global__ void __launch_bounds__(256, 2)
k_gemmln(const float2* __restrict__ x2,
         const float2* __restrict__ bias2,
         const float2* __restrict__ gamma2,
         const float2* __restrict__ beta2,
         float2* __restrict__ out2) {
    extern __shared__ __half sh[];
    __half* sA = sh;              // [128][LDA]
    __half* sB = sh + MB * LDA;   // [128][LDA]
    int t = threadIdx.x, lane = t & 31, warp = t >> 5;
    int n0 = blockIdx.x * MB;

    for (int i = t; i < MB * 16; i += 256) {
        int r = i >> 4, c = i & 15;
        uint4 v = (n0 + r < NN) ? g_nh4[(n0 + r) * 16 + c]
                                : make_uint4(0u, 0u, 0u, 0u);
        *(uint4*)&sA[r * LDA + c * 8] = v;
    }
    for (int i = t; i < DD * 16; i += 256) {
        int r = i >> 4, c = i & 15;
        *(uint4*)&sB[r * LDA + c * 8] = g_Wh4[r * 16 + c];
    }
    __syncthreads();

    int mr = warp * 16;
    int arow = mr + (lane & 15);
    int acol = (lane >> 4) * 8;
    unsigned af[8][4];
    #pragma unroll
    for (int kc = 0; kc < 8; kc++)
        ldsm_x4(af[kc], &sA[arow * LDA + kc * 16 + acol]);

    float acc[16][4];
    #pragma unroll
    for (int i = 0; i < 16; i++)
        #pragma unroll
        for (int j = 0; j < 4; j++) acc[i][j] = 0.f;

    int brow_off = (lane & 7) + ((lane >> 4) << 3);
    int bcol = lane & 8;
    #pragma unroll
    for (int p = 0; p < 8; p++) {
        int j0 = p * 16;
        #pragma unroll
        for (int kc = 0; kc < 8; kc++) {
            unsigned bf[4];
            ldsm_x4(bf, &sB[(j0 + brow_off) * LDA + kc * 16 + bcol]);
            mma16816(acc[2 * p],     af[kc], bf[0], bf[1]);
            mma16816(acc[2 * p + 1], af[kc], bf[2], bf[3]);
        }
    }

    int qrow = lane >> 2;
    int qcol = (lane & 3) * 2;
    int row_lo = n0 + mr + qrow;
    int row_hi = row_lo + 8;
    bool ok_lo = row_lo < NN, ok_hi = row_hi < NN;
    float s_lo = 0.f, ss_lo = 0.f, s_hi = 0.f, ss_hi = 0.f;
    #pragma unroll
    for (int t16 = 0; t16 < 16; t16++) {
        int n = (t16 >> 1) * 16 + (t16 & 1) * 8 + qcol;
        float2 bb = bias2[n >> 1];
        float2 xl = ok_lo ? x2[row_lo * 64 + (n >> 1)] : make_float2(0.f, 0.f);
        float2 xh = ok_hi ? x2[row_hi * 64 + (n >> 1)] : make_float2(0.f, 0.f);
        float h0 = acc[t16][0] + xl.x + bb.x;
        float h1 = acc[t16][1] + xl.y + bb.y;
        float h2 = acc[t16][2] + xh.x + bb.x;
        float h3 = acc[t16][3] + xh.y + bb.y;
        acc[t16][0] = h0; acc[t16][1] = h1; acc[t16][2] = h2; acc[t16][3] = h3;
        s_lo += h0 + h1; ss_lo += h0 * h0 + h1 * h1;
        s_hi += h2 + h3; ss_hi += h2 * h2 + h3 * h3;
    }
    #pragma unroll
    for (int o = 1; o <= 2; o <<= 1) {
        s_lo  += __shfl_xor_sync(0xffffffffu, s_lo,  o);
        ss_lo += __shfl_xor_sync(0xffffffffu, ss_lo, o);
        s_hi  += __shfl_xor_sync(0xffffffffu, s_hi,  o);
        ss_hi += __shfl_xor_sync(0xffffffffu, ss_hi, o);
    }
    float m_lo = s_lo * (1.0f / 128.0f);
    float v_lo = ss_lo * (1.0f / 128.0f) - m_lo * m_lo;
    float r_lo = rsqrtf(v_lo + LN_EPS);
    float m_hi = s_hi * (1.0f / 128.0f);
    float v_hi = ss_hi * (1.0f / 128.0f) - m_hi * m_hi;
    float r_hi = rsqrtf(v_hi + LN_EPS);

    #pragma unroll
    for (int t16 = 0; t16 < 16; t16++) {
        int n = (t16 >> 1) * 16 + (t16 & 1) * 8 + qcol;
        float2 gg = gamma2[n >> 1];
        float2 tt = beta2[n >> 1];
        if (ok_lo) {
            float2 o;
            o.x = (acc[t16][0] - m_lo) * r_lo * gg.x + tt.x;
            o.y = (acc[t16][1] - m_lo) * r_lo * gg.y + tt.y;
            out2[row_lo * 64 + (n >> 1)] = o;
        }
        if (ok_hi) {
            float2 o;
            o.x = (acc[t16][2] - m_hi) * r_hi * gg.x + tt.x;
            o.y = (acc[t16][3] - m_hi) * r_hi * gg.y + tt.y;
            out2[row_hi * 64 + (n >> 1)] = o;
        }
    }
}

// ---------------- launch -----------------------------------------------------
extern "C" void kernel_launch(void* const* d_in, const int* in_sizes, int n_in,
                              void* d_out, int out_size) {
    const float* x     = (const float*)d_in[0];
    const float* W     = (const float*)d_in[1];
    const float* bias  = (const float*)d_in[2];
    const float* gamma = (const float*)d_in[3];
    const float* beta  = (const float*)d_in[4];
    const int*   ei    = (const int*)d_in[5];
    const int4*  src4  = (const int4*)ei;
    const int4*  dst4  = (const int4*)(ei + NE);

    const int smem = (MB + DD) * LDA * (int)sizeof(__half);  // 69632B
    cudaFuncSetAttribute(k_gemmln, cudaFuncAttributeMaxDynamicSharedMemorySize, smem);

    const int conv_blks = (NN * 16 + DD * DD / 8 + 255) / 256;
    k_zero<<<(NN + 255) / 256, 256>>>();
    k_scatconv<<<SCAT_BLKS + conv_blks, 256>>>(src4, dst4,
                                               (const float4*)x,
                                               (const float4*)W);
    k_prep<<<(NN + 255) / 256, 256>>>();
    k_gather<<<(NN * 32 + 255) / 256, 256>>>();
    k_gemmln<<<(NN + MB - 1) / MB, 256, smem>>>(
        (const float2*)x, (const float2*)bias, (const float2*)gamma,
        (const float2*)beta, (float2*)d_out);
}